// round 2
// baseline (speedup 1.0000x reference)
#include <cuda_runtime.h>
#include <cuda_bf16.h>
#include <cstdint>

typedef unsigned long long ull_t;

// ---------------- scratch (device globals: no allocations allowed) ----------
__device__ float g_out1[256u * 1024u * 128u];   // layer-1 hidden states [B][T][128]
__device__ float g_h2[256 * 64];                // layer-2 final hidden  [B][64]

// ---------------- helpers ---------------------------------------------------
// expand a packed pair of bf16 (lo = w[2k], hi = w[2k+1]) to packed f32x2
__device__ __forceinline__ ull_t bf2f2(unsigned p) {
    unsigned lo = p << 16;
    unsigned hi = p & 0xffff0000u;
    ull_t r;
    asm("mov.b64 %0, {%1,%2};" : "=l"(r) : "r"(lo), "r"(hi));
    return r;
}

// packed dual-FMA: a = w*v + a (elementwise on 2 packed fp32 lanes)
__device__ __forceinline__ void fma2(ull_t& a, ull_t w, ull_t v) {
    asm("fma.rn.f32x2 %0, %1, %2, %0;" : "+l"(a) : "l"(w), "l"(v));
}

__device__ __forceinline__ float pairsum(ull_t a) {
    unsigned lo, hi;
    asm("mov.b64 {%0,%1}, %2;" : "=r"(lo), "=r"(hi) : "l"(a));
    return __uint_as_float(lo) + __uint_as_float(hi);
}

__device__ __forceinline__ float fast_rcp(float x) {
    float r;
    asm("rcp.approx.f32 %0, %1;" : "=f"(r) : "f"(x));
    return r;
}
__device__ __forceinline__ float sigmoid_f(float x) {
    return fast_rcp(1.0f + __expf(-x));
}
__device__ __forceinline__ float tanh_f(float x) {
    // tanh(x) = 1 - 2/(exp(2x)+1); saturates correctly at +/-inf
    return 1.0f - 2.0f * fast_rcp(1.0f + __expf(2.0f * x));
}

// ---------------- layer 1: persistent LSTM, 2 batches per CTA ---------------
// 512 threads: thread t owns gate row t (of 512 = 4*H rows), both batches.
// SMEM: weights [24 octets][512 rows] as uint4 of 4x bf16x2 (k-pairs), 192KB.
// sV[b][192] = [x_t (64) | h_t (128)].
__global__ void __launch_bounds__(512, 1) lstm1_kernel(
    const float* __restrict__ x,
    const float* __restrict__ Wih, const float* __restrict__ Whh,
    const float* __restrict__ bih, const float* __restrict__ bhh)
{
    extern __shared__ char smem[];
    uint4* sW  = (uint4*)smem;                       // [24][512] uint4 -> 196608 B
    float* sV0 = (float*)(smem + 196608);            // [192]
    float* sV1 = sV0 + 192;                          // [192]
    float* sG0 = sV1 + 192;                          // [512]
    float* sG1 = sG0 + 512;                          // [512]

    const int tid = threadIdx.x;
    const int b0 = blockIdx.x * 2;
    const int b1 = b0 + 1;

    // ---- stage weights (row = tid): combined row = [Wih row (64) | Whh row (128)]
    {
        const int r = tid;
        unsigned* sWu = (unsigned*)sW;
        #pragma unroll 1
        for (int kp = 0; kp < 96; kp++) {
            int k0 = 2 * kp, k1 = 2 * kp + 1;
            float w0 = (k0 < 64) ? Wih[r * 64 + k0] : Whh[r * 128 + (k0 - 64)];
            float w1 = (k1 < 64) ? Wih[r * 64 + k1] : Whh[r * 128 + (k1 - 64)];
            __nv_bfloat162 bb = __floats2bfloat162_rn(w0, w1);
            unsigned p = *(unsigned*)&bb;            // low 16 = w0, high 16 = w1
            sWu[(kp >> 2) * 2048 + r * 4 + (kp & 3)] = p;
        }
    }

    const float bias = bih[tid] + bhh[tid];

    // ---- init state: h = 0, stage x(t=0)
    if (tid < 128)               sV0[64 + tid]         = 0.0f;
    else if (tid < 256)          sV1[64 + (tid - 128)] = 0.0f;
    if (tid >= 256 && tid < 320) sV0[tid - 256] = x[(b0 * 1024 + 0) * 64 + (tid - 256)];
    if (tid >= 320 && tid < 384) sV1[tid - 320] = x[(b1 * 1024 + 0) * 64 + (tid - 320)];
    float c = 0.0f;   // cell state: thread tid<128 -> (b0, j=tid); 128..255 -> (b1, j=tid-128)
    __syncthreads();

    const uint4* wrow = sW + tid;                    // stride 512 per octet
    float* outp0 = g_out1 + (size_t)b0 * 1024 * 128;
    float* outp1 = g_out1 + (size_t)b1 * 1024 * 128;

    for (int t = 0; t < 1024; t++) {
        // prefetch next x into registers (latency overlapped with gate compute)
        float xpre = 0.0f;
        if (t + 1 < 1024) {
            if (tid >= 256 && tid < 320)      xpre = x[(b0 * 1024 + t + 1) * 64 + (tid - 256)];
            else if (tid >= 320 && tid < 384) xpre = x[(b1 * 1024 + t + 1) * 64 + (tid - 320)];
        }

        // gate pre-activation: dot(row, [x|h]) for both batches, packed f32x2
        ull_t a00 = 0, a01 = 0, a10 = 0, a11 = 0;
        #pragma unroll
        for (int kk = 0; kk < 24; kk++) {
            uint4 w = wrow[kk * 512];
            const ulonglong2* pv0 = (const ulonglong2*)(sV0 + 8 * kk);
            const ulonglong2* pv1 = (const ulonglong2*)(sV1 + 8 * kk);
            ulonglong2 va = pv0[0], vaa = pv0[1];
            ulonglong2 vb = pv1[0], vbb = pv1[1];
            ull_t e;
            e = bf2f2(w.x); fma2(a00, e, va.x);  fma2(a10, e, vb.x);
            e = bf2f2(w.y); fma2(a01, e, va.y);  fma2(a11, e, vb.y);
            e = bf2f2(w.z); fma2(a00, e, vaa.x); fma2(a10, e, vbb.x);
            e = bf2f2(w.w); fma2(a01, e, vaa.y); fma2(a11, e, vbb.y);
        }
        sG0[tid] = pairsum(a00) + pairsum(a01) + bias;
        sG1[tid] = pairsum(a10) + pairsum(a11) + bias;
        __syncthreads();

        // state update (threads 0..255) + x staging for t+1 (threads 256..383)
        if (tid < 256) {
            float* sG = (tid < 128) ? sG0 : sG1;
            float* sV = (tid < 128) ? sV0 : sV1;
            float* op = (tid < 128) ? outp0 : outp1;
            int j = tid & 127;
            float ig = sigmoid_f(sG[j]);
            float fg = sigmoid_f(sG[128 + j]);
            float gg = tanh_f(sG[256 + j]);
            float og = sigmoid_f(sG[384 + j]);
            c = fg * c + ig * gg;
            float h = og * tanh_f(c);
            sV[64 + j] = h;
            op[t * 128 + j] = h;
        } else if (tid < 320) {
            if (t + 1 < 1024) sV0[tid - 256] = xpre;
        } else if (tid < 384) {
            if (t + 1 < 1024) sV1[tid - 320] = xpre;
        }
        __syncthreads();
    }
}

// ---------------- layer 2: persistent LSTM, fp32 weights in SMEM ------------
// 256 threads: thread t owns gate row t (of 256 = 4*H2 rows), both batches.
// SMEM weights: [48 quads][256 rows] float4 (fp32) = 192KB. sV[b][192] = [h1_t(128) | h2(64)].
__global__ void __launch_bounds__(256, 1) lstm2_kernel(
    const float* __restrict__ Wih, const float* __restrict__ Whh,
    const float* __restrict__ bih, const float* __restrict__ bhh)
{
    extern __shared__ char smem[];
    float4* sW = (float4*)smem;                      // [48][256] float4 -> 196608 B
    float* sV0 = (float*)(smem + 196608);            // [192]
    float* sV1 = sV0 + 192;                          // [192]
    float* sG0 = sV1 + 192;                          // [256]
    float* sG1 = sG0 + 256;                          // [256]

    const int tid = threadIdx.x;
    const int b0 = blockIdx.x * 2;
    const int b1 = b0 + 1;
    const float* in0 = g_out1 + (size_t)b0 * 1024 * 128;
    const float* in1 = g_out1 + (size_t)b1 * 1024 * 128;

    // stage fp32 weights (row = tid): combined row = [Wih2 row (128) | Whh2 row (64)]
    {
        const int r = tid;
        #pragma unroll 1
        for (int q = 0; q < 48; q++) {
            float4 w;
            if (q < 32) w = *(const float4*)&Wih[r * 128 + 4 * q];
            else        w = *(const float4*)&Whh[r * 64 + (4 * q - 128)];
            sW[q * 256 + r] = w;
        }
    }

    const float bias = bih[tid] + bhh[tid];

    if (tid < 64)                     sV0[128 + tid]        = 0.0f;
    else if (tid < 128)               sV1[128 + (tid - 64)] = 0.0f;
    if (tid < 128) sV0[tid] = in0[tid];
    else           sV1[tid - 128] = in1[tid - 128];
    float c = 0.0f;   // thread tid<64 -> (b0, j=tid); 64..127 -> (b1, j=tid-64)
    float hfin = 0.0f;
    __syncthreads();

    for (int t = 0; t < 1024; t++) {
        float vpre = 0.0f;
        if (t + 1 < 1024)
            vpre = (tid < 128) ? in0[(t + 1) * 128 + tid] : in1[(t + 1) * 128 + (tid - 128)];

        ull_t a00 = 0, a01 = 0, a10 = 0, a11 = 0;
        const char* wbase = (const char*)(sW + tid);
        #pragma unroll
        for (int q = 0; q < 48; q++) {
            ulonglong2 w  = *(const ulonglong2*)(wbase + (size_t)q * 4096);
            ulonglong2 va = ((const ulonglong2*)sV0)[q];
            ulonglong2 vb = ((const ulonglong2*)sV1)[q];
            fma2(a00, w.x, va.x); fma2(a01, w.y, va.y);
            fma2(a10, w.x, vb.x); fma2(a11, w.y, vb.y);
        }
        sG0[tid] = pairsum(a00) + pairsum(a01) + bias;
        sG1[tid] = pairsum(a10) + pairsum(a11) + bias;
        __syncthreads();

        if (tid < 128) {
            float* sG = (tid < 64) ? sG0 : sG1;
            float* sV = (tid < 64) ? sV0 : sV1;
            int j = tid & 63;
            float ig = sigmoid_f(sG[j]);
            float fg = sigmoid_f(sG[64 + j]);
            float gg = tanh_f(sG[128 + j]);
            float og = sigmoid_f(sG[192 + j]);
            c = fg * c + ig * gg;
            float h = og * tanh_f(c);
            sV[128 + j] = h;
            hfin = h;
        }
        if (t + 1 < 1024) {
            if (tid < 128) sV0[tid] = vpre;
            else           sV1[tid - 128] = vpre;
        }
        __syncthreads();
    }

    if (tid < 128) {
        int j = tid & 63;
        int b = (tid < 64) ? b0 : b1;
        g_h2[b * 64 + j] = hfin;
    }
}

// ---------------- MLP head ---------------------------------------------------
__global__ void __launch_bounds__(256, 1) mlp_kernel(
    const float* __restrict__ W1, const float* __restrict__ b1,
    const float* __restrict__ W2, const float* __restrict__ b2,
    float* __restrict__ out)
{
    __shared__ float sW1[32 * 64];
    __shared__ float sb1[32];
    __shared__ float sW2[32];
    __shared__ float sb2;
    const int tid = threadIdx.x;
    for (int i = tid; i < 2048; i += 256) sW1[i] = W1[i];
    if (tid < 32) { sb1[tid] = b1[tid]; sW2[tid] = W2[tid]; }
    if (tid == 0) sb2 = b2[0];
    __syncthreads();

    float hv[64];
    #pragma unroll
    for (int k = 0; k < 16; k++)
        *(float4*)&hv[4 * k] = *(const float4*)&g_h2[tid * 64 + 4 * k];

    float acc = 0.0f;
    #pragma unroll 1
    for (int m = 0; m < 32; m++) {
        float d = sb1[m];
        #pragma unroll
        for (int k = 0; k < 64; k++) d += sW1[m * 64 + k] * hv[k];
        acc += sW2[m] * sigmoid_f(d);
    }
    out[tid] = sigmoid_f(acc + sb2);
}

// ---------------- launch ------------------------------------------------------
extern "C" void kernel_launch(void* const* d_in, const int* in_sizes, int n_in,
                              void* d_out, int out_size)
{
    const float* x    = (const float*)d_in[0];
    const float* Wih1 = (const float*)d_in[1];
    const float* Whh1 = (const float*)d_in[2];
    const float* bih1 = (const float*)d_in[3];
    const float* bhh1 = (const float*)d_in[4];
    const float* Wih2 = (const float*)d_in[5];
    const float* Whh2 = (const float*)d_in[6];
    const float* bih2 = (const float*)d_in[7];
    const float* bhh2 = (const float*)d_in[8];
    const float* W1   = (const float*)d_in[9];
    const float* b1   = (const float*)d_in[10];
    const float* W2   = (const float*)d_in[11];
    const float* b2   = (const float*)d_in[12];
    float* out = (float*)d_out;

    const size_t smem1 = 196608 + (2 * 192 + 2 * 512) * sizeof(float);  // 202240
    const size_t smem2 = 196608 + (2 * 192 + 2 * 256) * sizeof(float);  // 200192
    cudaFuncSetAttribute(lstm1_kernel, cudaFuncAttributeMaxDynamicSharedMemorySize, (int)smem1);
    cudaFuncSetAttribute(lstm2_kernel, cudaFuncAttributeMaxDynamicSharedMemorySize, (int)smem2);

    lstm1_kernel<<<128, 512, smem1>>>(x, Wih1, Whh1, bih1, bhh1);
    lstm2_kernel<<<128, 256, smem2>>>(Wih2, Whh2, bih2, bhh2);
    mlp_kernel<<<1, 256>>>(W1, b1, W2, b2, out);
}

// round 8
// speedup vs baseline: 2.9068x; 2.9068x over previous
#include <cuda_runtime.h>
#include <cuda_bf16.h>
#include <cstdint>

// ---------------- device scratch (no allocations allowed) -------------------
__device__ float g_h2[256 * 64];     // layer-2 final hidden [B][64]

// ---------------- SMEM map (dynamic) -----------------------------------------
// W1T: 32 mtiles x 12 ktiles x 512B tiles (each tile = 4x 128B blocks in
//      ldmatrix fragment order: [rows0-7,c0-7][rows8-15,c0-7][r0-7,c8-15][r8-15,c8-15])
#define W1T   0
#define V1O   196608                  // [8 n][200 bf16] rows padded to 400B
#define V2O   (196608 + 3200)         // [8 n][200 bf16]
#define SG1   (196608 + 6400)         // [512 rows][2 batches] f32 = 4096B
#define SG2   (SG1 + 4096)            // [256 rows][2 batches] f32 = 2048B
#define SMEMSZ (SG2 + 2048)           // 209152 B

#define VROW  400                     // bytes per V row (25*16: bank stride 4 -> conflict-free)

// ---------------- helpers ---------------------------------------------------
static __device__ __forceinline__ uint32_t smem_u32(const void* p) {
    uint32_t a;
    asm("{ .reg .u64 t; cvta.to.shared.u64 t, %1; cvt.u32.u64 %0, t; }" : "=r"(a) : "l"(p));
    return a;
}
static __device__ __forceinline__ float fast_rcp(float x) {
    float r; asm("rcp.approx.f32 %0,%1;" : "=f"(r) : "f"(x)); return r;
}
static __device__ __forceinline__ float sigmoid_f(float x) { return fast_rcp(1.f + __expf(-x)); }
static __device__ __forceinline__ float tanh_f(float x)    { return 1.f - 2.f * fast_rcp(1.f + __expf(2.f * x)); }

static __device__ __forceinline__ uint32_t packbf(float a, float b) {
    __nv_bfloat162 t = __floats2bfloat162_rn(a, b);   // a -> low 16, b -> high 16
    return *(uint32_t*)&t;
}

#define LDSM_X4(a0, a1, a2, a3, addr) \
    asm volatile("ldmatrix.sync.aligned.m8n8.x4.shared.b16 {%0,%1,%2,%3}, [%4];" \
                 : "=r"(a0), "=r"(a1), "=r"(a2), "=r"(a3) : "r"(addr))

#define HMMA(c0, c1, c2, c3, a0, a1, a2, a3, b0, b1) \
    asm volatile("mma.sync.aligned.m16n8k16.row.col.f32.bf16.bf16.f32 " \
                 "{%0,%1,%2,%3}, {%4,%5,%6,%7}, {%8,%9}, {%0,%1,%2,%3};" \
                 : "+f"(c0), "+f"(c1), "+f"(c2), "+f"(c3) \
                 : "r"(a0), "r"(a1), "r"(a2), "r"(a3), "r"(b0), "r"(b1))

static __device__ __forceinline__ uint32_t lds32(uint32_t addr) {
    uint32_t v; asm volatile("ld.shared.b32 %0, [%1];" : "=r"(v) : "r"(addr)); return v;
}

// ---------------- fused persistent LSTM (both layers, HMMA) -----------------
// 128 CTAs x 256 threads (8 warps). CTA owns batches (2*bid, 2*bid+1).
// Per step, 4 phases: L1-HMMA | L1-update (+x stage) | L2-HMMA | L2-update.
// W1 stationary in SMEM (bf16, ldmatrix tiles). W2 A-fragments in registers.
__global__ void __launch_bounds__(256, 1) lstm_fused_kernel(
    const float* __restrict__ x,
    const float* __restrict__ Wih1, const float* __restrict__ Whh1,
    const float* __restrict__ bih1, const float* __restrict__ bhh1,
    const float* __restrict__ Wih2, const float* __restrict__ Whh2,
    const float* __restrict__ bih2, const float* __restrict__ bhh2)
{
    extern __shared__ __align__(128) char smem[];
    const int tid  = threadIdx.x;
    const int wid  = tid >> 5;
    const int lane = tid & 31;
    const int gid  = lane >> 2;        // 0..7
    const int tid4 = lane & 3;         // 0..3
    const int b0   = blockIdx.x * 2;
    const uint32_t sb = smem_u32(smem);

    // ---- stage W1 -> SMEM bf16 in ldmatrix-block tile layout
    // combined row R (0..511) = [Wih1 row (64) | Whh1 row (128)], K = 192
    for (int idx = tid; idx < 49152; idx += 256) {
        int R = idx / 96, kp = idx % 96, k0 = 2 * kp;   // k0 even; pair never straddles 64
        float w0, w1;
        if (k0 < 64) { w0 = Wih1[R * 64 + k0];       w1 = Wih1[R * 64 + k0 + 1]; }
        else         { w0 = Whh1[R * 128 + k0 - 64]; w1 = Whh1[R * 128 + k0 - 63]; }
        int mt = R >> 4, kt = k0 >> 4, rr = R & 15, kk = k0 & 15;
        int blk = ((kk >> 3) << 1) | (rr >> 3);
        uint32_t off = (uint32_t)((mt * 12 + kt) * 4 + blk) * 128u
                     + (uint32_t)(rr & 7) * 16u + (uint32_t)(kk & 7) * 2u;
        *(uint32_t*)(smem + W1T + off) = packbf(w0, w1);
    }

    // ---- zero V1 + V2 (contiguous 6400 B)
    for (int i = tid; i < 6400 / 4; i += 256) ((uint32_t*)(smem + V1O))[i] = 0;

    // ---- W2 A-fragments -> registers (2 mtiles per warp, 12 ktiles, 4 regs)
    // combined row r (0..255) = [Wih2 row (128) | Whh2 row (64)], K = 192
    uint32_t wf[2][12][4];
    {
        #pragma unroll
        for (int m = 0; m < 2; m++) {
            int r = (wid * 2 + m) * 16 + gid;
            #pragma unroll
            for (int kt = 0; kt < 12; kt++) {
                int c = kt * 16 + tid4 * 2;
                #pragma unroll
                for (int q = 0; q < 4; q++) {
                    int rr = r + ((q & 1) ? 8 : 0);
                    int cc = c + ((q & 2) ? 8 : 0);
                    float v0 = (cc < 128) ? Wih2[rr * 128 + cc]     : Whh2[rr * 64 + cc - 128];
                    float v1 = (cc + 1 < 128) ? Wih2[rr * 128 + cc + 1] : Whh2[rr * 64 + cc - 127];
                    wf[m][kt][q] = packbf(v0, v1);
                }
            }
        }
    }

    // ---- biases
    float b1i = 0, b1f = 0, b1g = 0, b1o = 0;
    if (tid < 128) {
        b1i = bih1[tid] + bhh1[tid];
        b1f = bih1[128 + tid] + bhh1[128 + tid];
        b1g = bih1[256 + tid] + bhh1[256 + tid];
        b1o = bih1[384 + tid] + bhh1[384 + tid];
    }
    float b2i = 0, b2f = 0, b2g = 0, b2o = 0;
    if (tid < 64) {
        b2i = bih2[tid] + bhh2[tid];
        b2f = bih2[64 + tid] + bhh2[64 + tid];
        b2g = bih2[128 + tid] + bhh2[128 + tid];
        b2o = bih2[192 + tid] + bhh2[192 + tid];
    }

    __syncthreads();   // zeroing complete before x(0) staging

    // ---- x staging role (threads 128..255): thread owns (batch rb, col cx)
    const int xk = tid - 128;
    const int rb = xk >> 6, cx = xk & 63;
    if (tid >= 128)
        *(__nv_bfloat16*)(smem + V1O + rb * VROW + cx * 2) =
            __float2bfloat16(x[((b0 + rb) * 1024 + 0) * 64 + cx]);

    __syncthreads();   // W1 staged, V zeroed, x(0) in place

    float* sg1 = (float*)(smem + SG1);
    float* sg2 = (float*)(smem + SG2);
    const uint32_t v1u = sb + V1O + (uint32_t)gid * VROW + (uint32_t)tid4 * 4;
    const uint32_t v2u = sb + V2O + (uint32_t)gid * VROW + (uint32_t)tid4 * 4;
    const uint32_t w1u = sb + W1T + 128u * (uint32_t)(lane >> 3) + 16u * (uint32_t)(lane & 7);

    float c1a = 0.f, c1b = 0.f;            // L1 cell (tid<128: hidden j = tid)
    float c2a = 0.f, c2b = 0.f;            // L2 cell (tid<64:  hidden j = tid)
    float h2a = 0.f, h2b = 0.f;

    #pragma unroll 1
    for (int t = 0; t < 1024; t++) {
        // prefetch x(t+1) (gmem latency overlaps phases A-C)
        float xpre = 0.f;
        if (tid >= 128 && t + 1 < 1024)
            xpre = x[((b0 + rb) * 1024 + (t + 1)) * 64 + cx];

        // ---- Phase A: L1 HMMA  C[512x8] = W1[512x192] * V1^T
        {
            uint32_t f0[12], f1[12];
            #pragma unroll
            for (int kt = 0; kt < 12; kt++) {
                f0[kt] = lds32(v1u + (uint32_t)kt * 32u);
                f1[kt] = lds32(v1u + (uint32_t)kt * 32u + 16u);
            }
            #pragma unroll
            for (int i = 0; i < 4; i++) {
                const int mt = wid * 4 + i;
                float c0 = 0.f, c1 = 0.f, c2 = 0.f, c3 = 0.f;
                const uint32_t abase = w1u + (uint32_t)(mt * 12) * 512u;
                #pragma unroll
                for (int kt = 0; kt < 12; kt++) {
                    uint32_t a0, a1, a2, a3;
                    LDSM_X4(a0, a1, a2, a3, abase + (uint32_t)kt * 512u);
                    HMMA(c0, c1, c2, c3, a0, a1, a2, a3, f0[kt], f1[kt]);
                }
                if (tid4 == 0) {
                    int row = mt * 16 + gid;
                    *(float2*)(sg1 + 2 * row)       = make_float2(c0, c1);
                    *(float2*)(sg1 + 2 * (row + 8)) = make_float2(c2, c3);
                }
            }
        }
        __syncthreads();

        // ---- Phase B: L1 state update (tid<128) / x(t+1) staging (tid>=128)
        if (tid < 128) {
            const int j = tid;
            float2 gi = *(float2*)(sg1 + 2 * j);
            float2 gf = *(float2*)(sg1 + 2 * (128 + j));
            float2 gg = *(float2*)(sg1 + 2 * (256 + j));
            float2 go = *(float2*)(sg1 + 2 * (384 + j));
            // batch 0
            {
                float ig = sigmoid_f(gi.x + b1i);
                float fg = sigmoid_f(gf.x + b1f);
                float gv = tanh_f(gg.x + b1g);
                float og = sigmoid_f(go.x + b1o);
                c1a = fg * c1a + ig * gv;
                __nv_bfloat16 h = __float2bfloat16(og * tanh_f(c1a));
                *(__nv_bfloat16*)(smem + V1O + 0 * VROW + (64 + j) * 2) = h;
                *(__nv_bfloat16*)(smem + V2O + 0 * VROW + j * 2)        = h;
            }
            // batch 1
            {
                float ig = sigmoid_f(gi.y + b1i);
                float fg = sigmoid_f(gf.y + b1f);
                float gv = tanh_f(gg.y + b1g);
                float og = sigmoid_f(go.y + b1o);
                c1b = fg * c1b + ig * gv;
                __nv_bfloat16 h = __float2bfloat16(og * tanh_f(c1b));
                *(__nv_bfloat16*)(smem + V1O + 1 * VROW + (64 + j) * 2) = h;
                *(__nv_bfloat16*)(smem + V2O + 1 * VROW + j * 2)        = h;
            }
        } else if (t + 1 < 1024) {
            *(__nv_bfloat16*)(smem + V1O + rb * VROW + cx * 2) = __float2bfloat16(xpre);
        }
        __syncthreads();

        // ---- Phase C: L2 HMMA  C[256x8] = W2[256x192] * V2^T   (W2 in regs)
        {
            uint32_t f0[12], f1[12];
            #pragma unroll
            for (int kt = 0; kt < 12; kt++) {
                f0[kt] = lds32(v2u + (uint32_t)kt * 32u);
                f1[kt] = lds32(v2u + (uint32_t)kt * 32u + 16u);
            }
            #pragma unroll
            for (int m = 0; m < 2; m++) {
                float c0 = 0.f, c1 = 0.f, c2 = 0.f, c3 = 0.f;
                #pragma unroll
                for (int kt = 0; kt < 12; kt++)
                    HMMA(c0, c1, c2, c3, wf[m][kt][0], wf[m][kt][1],
                         wf[m][kt][2], wf[m][kt][3], f0[kt], f1[kt]);
                if (tid4 == 0) {
                    int row = (wid * 2 + m) * 16 + gid;
                    *(float2*)(sg2 + 2 * row)       = make_float2(c0, c1);
                    *(float2*)(sg2 + 2 * (row + 8)) = make_float2(c2, c3);
                }
            }
        }
        __syncthreads();

        // ---- Phase D: L2 state update (tid<64)
        if (tid < 64) {
            const int j = tid;
            float2 gi = *(float2*)(sg2 + 2 * j);
            float2 gf = *(float2*)(sg2 + 2 * (64 + j));
            float2 gg = *(float2*)(sg2 + 2 * (128 + j));
            float2 go = *(float2*)(sg2 + 2 * (192 + j));
            {
                float ig = sigmoid_f(gi.x + b2i);
                float fg = sigmoid_f(gf.x + b2f);
                float gv = tanh_f(gg.x + b2g);
                float og = sigmoid_f(go.x + b2o);
                c2a = fg * c2a + ig * gv;
                h2a = og * tanh_f(c2a);
                *(__nv_bfloat16*)(smem + V2O + 0 * VROW + (128 + j) * 2) = __float2bfloat16(h2a);
            }
            {
                float ig = sigmoid_f(gi.y + b2i);
                float fg = sigmoid_f(gf.y + b2f);
                float gv = tanh_f(gg.y + b2g);
                float og = sigmoid_f(go.y + b2o);
                c2b = fg * c2b + ig * gv;
                h2b = og * tanh_f(c2b);
                *(__nv_bfloat16*)(smem + V2O + 1 * VROW + (128 + j) * 2) = __float2bfloat16(h2b);
            }
        }
        __syncthreads();
    }

    if (tid < 64) {
        g_h2[(b0 + 0) * 64 + tid] = h2a;
        g_h2[(b0 + 1) * 64 + tid] = h2b;
    }
}

// ---------------- MLP head ----------------------------------------------------
__global__ void __launch_bounds__(256, 1) mlp_kernel(
    const float* __restrict__ W1, const float* __restrict__ b1,
    const float* __restrict__ W2, const float* __restrict__ b2,
    float* __restrict__ out)
{
    __shared__ float sW1[32 * 64];
    __shared__ float sb1[32];
    __shared__ float sW2[32];
    __shared__ float sb2;
    const int tid = threadIdx.x;
    for (int i = tid; i < 2048; i += 256) sW1[i] = W1[i];
    if (tid < 32) { sb1[tid] = b1[tid]; sW2[tid] = W2[tid]; }
    if (tid == 0) sb2 = b2[0];
    __syncthreads();

    float hv[64];
    #pragma unroll
    for (int k = 0; k < 16; k++)
        *(float4*)&hv[4 * k] = *(const float4*)&g_h2[tid * 64 + 4 * k];

    float acc = 0.0f;
    #pragma unroll 1
    for (int m = 0; m < 32; m++) {
        float d = sb1[m];
        #pragma unroll
        for (int k = 0; k < 64; k++) d += sW1[m * 64 + k] * hv[k];
        acc += sW2[m] * sigmoid_f(d);
    }
    out[tid] = sigmoid_f(acc + sb2);
}

// ---------------- launch ------------------------------------------------------
extern "C" void kernel_launch(void* const* d_in, const int* in_sizes, int n_in,
                              void* d_out, int out_size)
{
    const float* x    = (const float*)d_in[0];
    const float* Wih1 = (const float*)d_in[1];
    const float* Whh1 = (const float*)d_in[2];
    const float* bih1 = (const float*)d_in[3];
    const float* bhh1 = (const float*)d_in[4];
    const float* Wih2 = (const float*)d_in[5];
    const float* Whh2 = (const float*)d_in[6];
    const float* bih2 = (const float*)d_in[7];
    const float* bhh2 = (const float*)d_in[8];
    const float* W1   = (const float*)d_in[9];
    const float* b1   = (const float*)d_in[10];
    const float* W2   = (const float*)d_in[11];
    const float* b2   = (const float*)d_in[12];
    float* out = (float*)d_out;

    cudaFuncSetAttribute(lstm_fused_kernel,
                         cudaFuncAttributeMaxDynamicSharedMemorySize, SMEMSZ);

    lstm_fused_kernel<<<128, 256, SMEMSZ>>>(x, Wih1, Whh1, bih1, bhh1,
                                            Wih2, Whh2, bih2, bhh2);
    mlp_kernel<<<1, 256>>>(W1, b1, W2, b2, out);
}

// round 14
// speedup vs baseline: 3.0172x; 1.0380x over previous
#include <cuda_runtime.h>
#include <cuda_bf16.h>
#include <cstdint>

// ---------------- device scratch (no allocations allowed) -------------------
__device__ float g_h2[256 * 64];     // layer-2 final hidden [B][64]

// ---------------- SMEM map (dynamic) -----------------------------------------
// W1T: 32 mtiles x 12 ktiles x 512B tiles (each tile = 4x 128B blocks in
//      ldmatrix fragment order: [rows0-7,c0-7][rows8-15,c0-7][r0-7,c8-15][r8-15,c8-15])
#define W1T   0
#define V1O   196608                  // [8 n][200 bf16] rows padded to 400B
#define V2O   (196608 + 3200)         // [8 n][200 bf16]
#define SG1   (196608 + 6400)         // [512 rows][2 batches] f32 = 4096B
#define SG2   (SG1 + 4096)            // [256 rows][2 batches] f32 = 2048B
#define SMEMSZ (SG2 + 2048)           // 209152 B

#define VROW  400                     // bytes per V row (25*16: bank stride 4 -> conflict-free)

// ---------------- helpers ---------------------------------------------------
static __device__ __forceinline__ uint32_t smem_u32(const void* p) {
    uint32_t a;
    asm("{ .reg .u64 t; cvta.to.shared.u64 t, %1; cvt.u32.u64 %0, t; }" : "=r"(a) : "l"(p));
    return a;
}
static __device__ __forceinline__ float fast_rcp(float x) {
    float r; asm("rcp.approx.f32 %0,%1;" : "=f"(r) : "f"(x)); return r;
}
static __device__ __forceinline__ float sigmoid_f(float x) { return fast_rcp(1.f + __expf(-x)); }
static __device__ __forceinline__ float tanh_f(float x)    { return 1.f - 2.f * fast_rcp(1.f + __expf(2.f * x)); }

static __device__ __forceinline__ uint32_t packbf(float a, float b) {
    __nv_bfloat162 t = __floats2bfloat162_rn(a, b);   // a -> low 16, b -> high 16
    return *(uint32_t*)&t;
}

#define LDSM_X4(a0, a1, a2, a3, addr) \
    asm volatile("ldmatrix.sync.aligned.m8n8.x4.shared.b16 {%0,%1,%2,%3}, [%4];" \
                 : "=r"(a0), "=r"(a1), "=r"(a2), "=r"(a3) : "r"(addr))

#define HMMA(c0, c1, c2, c3, a0, a1, a2, a3, b0, b1) \
    asm volatile("mma.sync.aligned.m16n8k16.row.col.f32.bf16.bf16.f32 " \
                 "{%0,%1,%2,%3}, {%4,%5,%6,%7}, {%8,%9}, {%0,%1,%2,%3};" \
                 : "+f"(c0), "+f"(c1), "+f"(c2), "+f"(c3) \
                 : "r"(a0), "r"(a1), "r"(a2), "r"(a3), "r"(b0), "r"(b1))

static __device__ __forceinline__ uint32_t lds32(uint32_t addr) {
    uint32_t v; asm volatile("ld.shared.b32 %0, [%1];" : "=r"(v) : "r"(addr)); return v;
}

// ---------------- fused persistent LSTM (pipelined, HMMA) -------------------
// 128 CTAs x 256 threads (8 warps). CTA owns batches (2*bid, 2*bid+1).
// Software pipeline: iteration s runs L1 MMA for t=s AND L2 MMA for t=s-1 in
// ONE phase (L2 uses register-resident W2 frags, hides under L1's LDSM), then
// ONE update phase: h1(s) [tid<128] | h2(s-1) [tid 128..191] | x stage [tid>=192].
// 2 barriers/step instead of 4.
__global__ void __launch_bounds__(256, 1) lstm_fused_kernel(
    const float* __restrict__ x,
    const float* __restrict__ Wih1, const float* __restrict__ Whh1,
    const float* __restrict__ bih1, const float* __restrict__ bhh1,
    const float* __restrict__ Wih2, const float* __restrict__ Whh2,
    const float* __restrict__ bih2, const float* __restrict__ bhh2)
{
    extern __shared__ __align__(128) char smem[];
    const int tid  = threadIdx.x;
    const int wid  = tid >> 5;
    const int lane = tid & 31;
    const int gid  = lane >> 2;        // 0..7
    const int tid4 = lane & 3;         // 0..3
    const int b0   = blockIdx.x * 2;
    const uint32_t sb = smem_u32(smem);

    // ---- stage W1 -> SMEM bf16 in ldmatrix-block tile layout
    for (int idx = tid; idx < 49152; idx += 256) {
        int R = idx / 96, kp = idx % 96, k0 = 2 * kp;
        float w0, w1;
        if (k0 < 64) { w0 = Wih1[R * 64 + k0];       w1 = Wih1[R * 64 + k0 + 1]; }
        else         { w0 = Whh1[R * 128 + k0 - 64]; w1 = Whh1[R * 128 + k0 - 63]; }
        int mt = R >> 4, kt = k0 >> 4, rr = R & 15, kk = k0 & 15;
        int blk = ((kk >> 3) << 1) | (rr >> 3);
        uint32_t off = (uint32_t)((mt * 12 + kt) * 4 + blk) * 128u
                     + (uint32_t)(rr & 7) * 16u + (uint32_t)(kk & 7) * 2u;
        *(uint32_t*)(smem + W1T + off) = packbf(w0, w1);
    }

    // ---- zero V1 + V2 (contiguous 6400 B)
    for (int i = tid; i < 6400 / 4; i += 256) ((uint32_t*)(smem + V1O))[i] = 0;

    // ---- W2 A-fragments -> registers (2 mtiles per warp, 12 ktiles, 4 regs)
    uint32_t wf[2][12][4];
    {
        #pragma unroll
        for (int m = 0; m < 2; m++) {
            int r = (wid * 2 + m) * 16 + gid;
            #pragma unroll
            for (int kt = 0; kt < 12; kt++) {
                int c = kt * 16 + tid4 * 2;
                #pragma unroll
                for (int q = 0; q < 4; q++) {
                    int rr = r + ((q & 1) ? 8 : 0);
                    int cc = c + ((q & 2) ? 8 : 0);
                    float v0 = (cc < 128) ? Wih2[rr * 128 + cc]     : Whh2[rr * 64 + cc - 128];
                    float v1 = (cc + 1 < 128) ? Wih2[rr * 128 + cc + 1] : Whh2[rr * 64 + cc - 127];
                    wf[m][kt][q] = packbf(v0, v1);
                }
            }
        }
    }

    // ---- biases (role-split)
    float b1i = 0, b1f = 0, b1g = 0, b1o = 0;
    if (tid < 128) {
        b1i = bih1[tid] + bhh1[tid];
        b1f = bih1[128 + tid] + bhh1[128 + tid];
        b1g = bih1[256 + tid] + bhh1[256 + tid];
        b1o = bih1[384 + tid] + bhh1[384 + tid];
    }
    float b2i = 0, b2f = 0, b2g = 0, b2o = 0;
    if (tid >= 128 && tid < 192) {
        int j = tid - 128;
        b2i = bih2[j] + bhh2[j];
        b2f = bih2[64 + j] + bhh2[64 + j];
        b2g = bih2[128 + j] + bhh2[128 + j];
        b2o = bih2[192 + j] + bhh2[192 + j];
    }

    __syncthreads();   // zeroing complete before x(0) staging

    // ---- x staging role (tid 192..255): thread owns col k, both batches
    const int xk = tid - 192;
    if (tid >= 192) {
        *(__nv_bfloat16*)(smem + V1O + 0 * VROW + xk * 2) =
            __float2bfloat16(x[((b0 + 0) * 1024 + 0) * 64 + xk]);
        *(__nv_bfloat16*)(smem + V1O + 1 * VROW + xk * 2) =
            __float2bfloat16(x[((b0 + 1) * 1024 + 0) * 64 + xk]);
    }

    __syncthreads();   // W1 staged, V zeroed, x(0) in place

    float* sg1 = (float*)(smem + SG1);
    float* sg2 = (float*)(smem + SG2);
    const uint32_t v1u = sb + V1O + (uint32_t)gid * VROW + (uint32_t)tid4 * 4;
    const uint32_t v2u = sb + V2O + (uint32_t)gid * VROW + (uint32_t)tid4 * 4;
    const uint32_t w1u = sb + W1T + 128u * (uint32_t)(lane >> 3) + 16u * (uint32_t)(lane & 7);

    float c1a = 0.f, c1b = 0.f;            // L1 cell (tid<128: hidden j = tid)
    float c2a = 0.f, c2b = 0.f;            // L2 cell (tid 128..191: hidden j = tid-128)
    float h2a = 0.f, h2b = 0.f;

    #pragma unroll 1
    for (int s = 0; s < 1025; s++) {
        // prefetch x(s+1)
        float xpa = 0.f, xpb = 0.f;
        if (tid >= 192 && s + 1 < 1024) {
            xpa = x[((b0 + 0) * 1024 + (s + 1)) * 64 + xk];
            xpb = x[((b0 + 1) * 1024 + (s + 1)) * 64 + xk];
        }

        // ---- Phase A: L2 HMMA (t=s-1, reg A-frags) + L1 HMMA (t=s, LDSM)
        {
            // L2: gates from V2 = [h1(s-1) | h2(s-2)]
            uint32_t e0[12], e1[12];
            #pragma unroll
            for (int kt = 0; kt < 12; kt++) {
                e0[kt] = lds32(v2u + (uint32_t)kt * 32u);
                e1[kt] = lds32(v2u + (uint32_t)kt * 32u + 16u);
            }
            #pragma unroll
            for (int m = 0; m < 2; m++) {
                float d0 = 0.f, d1 = 0.f, d2 = 0.f, d3 = 0.f;
                #pragma unroll
                for (int kt = 0; kt < 12; kt++)
                    HMMA(d0, d1, d2, d3, wf[m][kt][0], wf[m][kt][1],
                         wf[m][kt][2], wf[m][kt][3], e0[kt], e1[kt]);
                if (tid4 == 0) {
                    int row = (wid * 2 + m) * 16 + gid;
                    *(float2*)(sg2 + 2 * row)       = make_float2(d0, d1);
                    *(float2*)(sg2 + 2 * (row + 8)) = make_float2(d2, d3);
                }
            }

            // L1: gates from V1 = [x(s) | h1(s-1)]
            if (s < 1024) {
                uint32_t f0[12], f1[12];
                #pragma unroll
                for (int kt = 0; kt < 12; kt++) {
                    f0[kt] = lds32(v1u + (uint32_t)kt * 32u);
                    f1[kt] = lds32(v1u + (uint32_t)kt * 32u + 16u);
                }
                #pragma unroll
                for (int i = 0; i < 4; i++) {
                    const int mt = wid * 4 + i;
                    float c0 = 0.f, c1 = 0.f, c2 = 0.f, c3 = 0.f;
                    const uint32_t abase = w1u + (uint32_t)(mt * 12) * 512u;
                    #pragma unroll
                    for (int kt = 0; kt < 12; kt++) {
                        uint32_t a0, a1, a2, a3;
                        LDSM_X4(a0, a1, a2, a3, abase + (uint32_t)kt * 512u);
                        HMMA(c0, c1, c2, c3, a0, a1, a2, a3, f0[kt], f1[kt]);
                    }
                    if (tid4 == 0) {
                        int row = mt * 16 + gid;
                        *(float2*)(sg1 + 2 * row)       = make_float2(c0, c1);
                        *(float2*)(sg1 + 2 * (row + 8)) = make_float2(c2, c3);
                    }
                }
            }
        }
        __syncthreads();

        // ---- Phase B: h1(s) | h2(s-1) | x(s+1) staging, concurrently
        if (tid < 128) {
            if (s < 1024) {
                const int j = tid;
                float2 gi = *(float2*)(sg1 + 2 * j);
                float2 gf = *(float2*)(sg1 + 2 * (128 + j));
                float2 gg = *(float2*)(sg1 + 2 * (256 + j));
                float2 go = *(float2*)(sg1 + 2 * (384 + j));
                {
                    float ig = sigmoid_f(gi.x + b1i);
                    float fg = sigmoid_f(gf.x + b1f);
                    float gv = tanh_f(gg.x + b1g);
                    float og = sigmoid_f(go.x + b1o);
                    c1a = fg * c1a + ig * gv;
                    __nv_bfloat16 h = __float2bfloat16(og * tanh_f(c1a));
                    *(__nv_bfloat16*)(smem + V1O + 0 * VROW + (64 + j) * 2) = h;
                    *(__nv_bfloat16*)(smem + V2O + 0 * VROW + j * 2)        = h;
                }
                {
                    float ig = sigmoid_f(gi.y + b1i);
                    float fg = sigmoid_f(gf.y + b1f);
                    float gv = tanh_f(gg.y + b1g);
                    float og = sigmoid_f(go.y + b1o);
                    c1b = fg * c1b + ig * gv;
                    __nv_bfloat16 h = __float2bfloat16(og * tanh_f(c1b));
                    *(__nv_bfloat16*)(smem + V1O + 1 * VROW + (64 + j) * 2) = h;
                    *(__nv_bfloat16*)(smem + V2O + 1 * VROW + j * 2)        = h;
                }
            }
        } else if (tid < 192) {
            if (s > 0) {
                const int j = tid - 128;
                float2 gi = *(float2*)(sg2 + 2 * j);
                float2 gf = *(float2*)(sg2 + 2 * (64 + j));
                float2 gg = *(float2*)(sg2 + 2 * (128 + j));
                float2 go = *(float2*)(sg2 + 2 * (192 + j));
                {
                    float ig = sigmoid_f(gi.x + b2i);
                    float fg = sigmoid_f(gf.x + b2f);
                    float gv = tanh_f(gg.x + b2g);
                    float og = sigmoid_f(go.x + b2o);
                    c2a = fg * c2a + ig * gv;
                    h2a = og * tanh_f(c2a);
                    *(__nv_bfloat16*)(smem + V2O + 0 * VROW + (128 + j) * 2) = __float2bfloat16(h2a);
                }
                {
                    float ig = sigmoid_f(gi.y + b2i);
                    float fg = sigmoid_f(gf.y + b2f);
                    float gv = tanh_f(gg.y + b2g);
                    float og = sigmoid_f(go.y + b2o);
                    c2b = fg * c2b + ig * gv;
                    h2b = og * tanh_f(c2b);
                    *(__nv_bfloat16*)(smem + V2O + 1 * VROW + (128 + j) * 2) = __float2bfloat16(h2b);
                }
            }
        } else {
            if (s + 1 < 1024) {
                *(__nv_bfloat16*)(smem + V1O + 0 * VROW + xk * 2) = __float2bfloat16(xpa);
                *(__nv_bfloat16*)(smem + V1O + 1 * VROW + xk * 2) = __float2bfloat16(xpb);
            }
        }
        __syncthreads();
    }

    if (tid >= 128 && tid < 192) {
        const int j = tid - 128;
        g_h2[(b0 + 0) * 64 + j] = h2a;
        g_h2[(b0 + 1) * 64 + j] = h2b;
    }
}

// ---------------- MLP head ----------------------------------------------------
__global__ void __launch_bounds__(256, 1) mlp_kernel(
    const float* __restrict__ W1, const float* __restrict__ b1,
    const float* __restrict__ W2, const float* __restrict__ b2,
    float* __restrict__ out)
{
    __shared__ float sW1[32 * 64];
    __shared__ float sb1[32];
    __shared__ float sW2[32];
    __shared__ float sb2;
    const int tid = threadIdx.x;
    for (int i = tid; i < 2048; i += 256) sW1[i] = W1[i];
    if (tid < 32) { sb1[tid] = b1[tid]; sW2[tid] = W2[tid]; }
    if (tid == 0) sb2 = b2[0];
    __syncthreads();

    float hv[64];
    #pragma unroll
    for (int k = 0; k < 16; k++)
        *(float4*)&hv[4 * k] = *(const float4*)&g_h2[tid * 64 + 4 * k];

    float acc = 0.0f;
    #pragma unroll 1
    for (int m = 0; m < 32; m++) {
        float d = sb1[m];
        #pragma unroll
        for (int k = 0; k < 64; k++) d += sW1[m * 64 + k] * hv[k];
        acc += sW2[m] * sigmoid_f(d);
    }
    out[tid] = sigmoid_f(acc + sb2);
}

// ---------------- launch ------------------------------------------------------
extern "C" void kernel_launch(void* const* d_in, const int* in_sizes, int n_in,
                              void* d_out, int out_size)
{
    const float* x    = (const float*)d_in[0];
    const float* Wih1 = (const float*)d_in[1];
    const float* Whh1 = (const float*)d_in[2];
    const float* bih1 = (const float*)d_in[3];
    const float* bhh1 = (const float*)d_in[4];
    const float* Wih2 = (const float*)d_in[5];
    const float* Whh2 = (const float*)d_in[6];
    const float* bih2 = (const float*)d_in[7];
    const float* bhh2 = (const float*)d_in[8];
    const float* W1   = (const float*)d_in[9];
    const float* b1   = (const float*)d_in[10];
    const float* W2   = (const float*)d_in[11];
    const float* b2   = (const float*)d_in[12];
    float* out = (float*)d_out;

    cudaFuncSetAttribute(lstm_fused_kernel,
                         cudaFuncAttributeMaxDynamicSharedMemorySize, SMEMSZ);

    lstm_fused_kernel<<<128, 256, SMEMSZ>>>(x, Wih1, Whh1, bih1, bhh1,
                                            Wih2, Whh2, bih2, bhh2);
    mlp_kernel<<<1, 256>>>(W1, b1, W2, b2, out);
}